// round 9
// baseline (speedup 1.0000x reference)
#include <cuda_runtime.h>
#include <math.h>

typedef unsigned long long u64;

constexpr int D       = 272;      // capsule feature dim
constexpr int NC      = 19;       // num classes
constexpr int NCP     = 20;       // padded classes (10 f32x2 pairs)
constexpr int PSTRIDE = 32;       // padded proj row (128B aligned)
constexpr int G_MAX   = 65536;    // B*H*W grid cells
constexpr int BLK     = 128;      // threads per block (proj)
constexpr int RPB     = 256;      // rows per block (2 per thread)
constexpr int CHK     = 16;       // k-chunk (272 = 17 * 16)
constexpr int TPAD    = 20;       // sT row stride (floats)

__device__ float g_proj[(size_t)G_MAX * PSTRIDE];   // 8.4 MB scratch (L2-resident)

// ---- f32x2 helpers (ptxas won't emit FFMA2 from C++; PTX only) ------------
__device__ __forceinline__ u64 pack_dup(float v) {
    u64 r; unsigned u = __float_as_uint(v);
    asm("mov.b64 %0, {%1, %2};" : "=l"(r) : "r"(u), "r"(u));
    return r;
}
__device__ __forceinline__ u64 fma2(u64 a, u64 b, u64 c) {
    u64 d; asm("fma.rn.f32x2 %0, %1, %2, %3;" : "=l"(d) : "l"(a), "l"(b), "l"(c));
    return d;
}
__device__ __forceinline__ float2 unpack2(u64 v) {
    unsigned lo, hi;
    asm("mov.b64 {%0, %1}, %2;" : "=r"(lo), "=r"(hi) : "l"(v));
    return make_float2(__uint_as_float(lo), __uint_as_float(hi));
}

// ---------------------------------------------------------------------------
// Kernel A: proj = feats @ W  (G x 272)@(272 x 19) -> (G x 32-padded).
// 128 threads x 2 rows. Accumulators packed across class pairs (f32x2):
// per k: 2 dup-packs + 10 uniform LDS.64 (W pairs, contiguous in row-major W)
// + 20 FFMA2  (vs 38 FFMA before -> FMA-pipe time halved).
// ---------------------------------------------------------------------------
__global__ __launch_bounds__(BLK, 3)
void proj_kernel(const float* __restrict__ feats, const float* __restrict__ Wm) {
    __shared__ float sW[D * NCP];        // W padded to 20 cols, 21.8 KB
    __shared__ float sT[RPB * TPAD];     // 256 rows x 16 k, stride 20, 20 KB

    const int tid  = threadIdx.x;
    const int base = blockIdx.x * RPB;

    for (int i = tid; i < D * NCP; i += BLK) {
        int k = i / NCP, c = i % NCP;
        sW[i] = (c < NC) ? Wm[k * NC + c] : 0.f;
    }

    u64 acc0[NCP / 2], acc1[NCP / 2];
    #pragma unroll
    for (int p = 0; p < NCP / 2; ++p) { acc0[p] = 0ull; acc1[p] = 0ull; }

    const float4* f4 = reinterpret_cast<const float4*>(feats);
    const int r0 = tid, r1 = tid + BLK;

    for (int ch = 0; ch < D / CHK; ++ch) {
        const int d4 = ch * (CHK / 4);
        __syncthreads();                 // prev-chunk reads done (covers sW iter 0)
        #pragma unroll
        for (int qq = 0; qq < 8; ++qq) {
            int i   = tid + qq * BLK;    // 0..1023 -> 256 rows x 4 float4
            int r   = i >> 2;
            int sub = i & 3;
            float4 v = f4[(size_t)(base + r) * (D / 4) + d4 + sub];
            reinterpret_cast<float4*>(&sT[r * TPAD + sub * 4])[0] = v;
        }
        __syncthreads();
        const float4* sT4 = reinterpret_cast<const float4*>(sT);
        #pragma unroll
        for (int k4 = 0; k4 < CHK / 4; ++k4) {
            float4 a = sT4[r0 * (TPAD / 4) + k4];   // 8-lane phases conflict-free
            float4 b = sT4[r1 * (TPAD / 4) + k4];
            const float av[4] = {a.x, a.y, a.z, a.w};
            const float bv[4] = {b.x, b.y, b.z, b.w};
            #pragma unroll
            for (int kk = 0; kk < 4; ++kk) {
                const int k = ch * CHK + k4 * 4 + kk;
                const u64* w2 = reinterpret_cast<const u64*>(&sW[k * NCP]);
                u64 aa = pack_dup(av[kk]);
                u64 bb = pack_dup(bv[kk]);
                #pragma unroll
                for (int p = 0; p < NCP / 2; ++p) {
                    u64 w = w2[p];                   // LDS.64 uniform broadcast
                    acc0[p] = fma2(aa, w, acc0[p]);
                    acc1[p] = fma2(bb, w, acc1[p]);
                }
            }
        }
    }

    // Unpack and write both rows (rows 128B-aligned in g_proj).
    float* o0 = &g_proj[(size_t)(base + r0) * PSTRIDE];
    float* o1 = &g_proj[(size_t)(base + r1) * PSTRIDE];
    #pragma unroll
    for (int q = 0; q < 2; ++q) {
        const u64* acc = q ? acc1 : acc0;
        float* o = q ? o1 : o0;
        float v[NCP];
        #pragma unroll
        for (int p = 0; p < NCP / 2; ++p) {
            float2 f = unpack2(acc[p]);
            v[2 * p] = f.x; v[2 * p + 1] = f.y;
        }
        #pragma unroll
        for (int c4 = 0; c4 < 4; ++c4)
            reinterpret_cast<float4*>(o)[c4] =
                make_float4(v[c4*4], v[c4*4+1], v[c4*4+2], v[c4*4+3]);
        o[16] = v[16]; o[17] = v[17]; o[18] = v[18];
    }
}

// ---------------------------------------------------------------------------
// Kernel B: 8 segments per block (1 warp each). Boundaries found inline by
// binary search on sorted seg_ids (9 searches per block, amortized). Then
// sum 19-float proj rows (L2-resident), mean, bias, sigmoid.
// ---------------------------------------------------------------------------
__global__ __launch_bounds__(256, 8)
void pool_kernel(const int* __restrict__ point_idx,
                 const int* __restrict__ seg_ids,
                 const float* __restrict__ bias,
                 float* __restrict__ out, int NI, int P)
{
    __shared__ int sb[9];
    const int tid = threadIdx.x;
    const int s0  = blockIdx.x * 8;

    if (tid < 9) {
        int target = s0 + tid;
        int lo = 0, hi = P;
        while (lo < hi) {                      // lower_bound(seg_ids, target)
            int mid = (lo + hi) >> 1;
            if (seg_ids[mid] < target) lo = mid + 1; else hi = mid;
        }
        sb[tid] = lo;
    }
    __syncthreads();

    const int w     = tid >> 5;
    const int seg   = s0 + w;
    if (seg >= NI) return;
    const int lane  = tid & 31;
    const int start = sb[w];
    const int end   = sb[w + 1];

    float acc = 0.f;
    for (int b = start; b < end; b += 32) {
        const int n = min(32, end - b);
        int myidx = (lane < n) ? point_idx[b + lane] : 0;
        int j = 0;
        for (; j + 4 <= n; j += 4) {
            int i0 = __shfl_sync(0xffffffffu, myidx, j);
            int i1 = __shfl_sync(0xffffffffu, myidx, j + 1);
            int i2 = __shfl_sync(0xffffffffu, myidx, j + 2);
            int i3 = __shfl_sync(0xffffffffu, myidx, j + 3);
            if (lane < NC) {
                float v0 = g_proj[(size_t)i0 * PSTRIDE + lane];
                float v1 = g_proj[(size_t)i1 * PSTRIDE + lane];
                float v2 = g_proj[(size_t)i2 * PSTRIDE + lane];
                float v3 = g_proj[(size_t)i3 * PSTRIDE + lane];
                acc += (v0 + v1) + (v2 + v3);
            }
        }
        for (; j < n; ++j) {
            int i0 = __shfl_sync(0xffffffffu, myidx, j);
            if (lane < NC) acc += g_proj[(size_t)i0 * PSTRIDE + lane];
        }
    }

    if (lane < NC) {
        const int cnt = max(end - start, 1);
        float z = acc / (float)cnt + bias[lane];
        out[seg * NC + lane] = 1.0f / (1.0f + expf(-z));
    }
}

// ---------------------------------------------------------------------------
// Launch
// ---------------------------------------------------------------------------
extern "C" void kernel_launch(void* const* d_in, const int* in_sizes, int n_in,
                              void* d_out, int out_size) {
    const float* feats     = (const float*)d_in[0];   // [G, D]
    const float* Wmat      = (const float*)d_in[1];   // [D, NC]
    const float* bias      = (const float*)d_in[2];   // [NC]
    const int*   point_idx = (const int*)  d_in[3];   // [P]
    const int*   seg_ids   = (const int*)  d_in[4];   // [P] sorted
    float*       out       = (float*)d_out;           // [NI, NC]

    const int P = in_sizes[3];
    int G  = in_sizes[0] / D;                         // 65536
    if (G > G_MAX) G = G_MAX;
    const int NI = out_size / NC;                     // 4096

    proj_kernel<<<G / RPB, BLK>>>(feats, Wmat);
    pool_kernel<<<(NI + 7) / 8, 256>>>(point_idx, seg_ids, bias, out, NI, P);
}

// round 11
// speedup vs baseline: 1.1286x; 1.1286x over previous
#include <cuda_runtime.h>
#include <math.h>

typedef unsigned long long u64;

constexpr int D       = 272;      // capsule feature dim
constexpr int NC      = 19;       // num classes
constexpr int NCP     = 20;       // padded classes (10 f32x2 pairs)
constexpr int PSTRIDE = 32;       // padded proj row (128B aligned)
constexpr int G_MAX   = 65536;    // B*H*W grid cells
constexpr int BLK     = 128;      // threads per block (proj)
constexpr int RPB     = 256;      // rows per block (2 per thread)
constexpr int CHK     = 16;       // k-chunk (272 = 17 * 16)
constexpr int TPAD    = 20;       // sT row stride (floats)

__device__ float g_proj[(size_t)G_MAX * PSTRIDE];   // 8.4 MB scratch (L2-resident)

// ---- f32x2 helpers (ptxas won't emit FFMA2 from C++; PTX only) ------------
__device__ __forceinline__ u64 pack_dup(float v) {
    u64 r; unsigned u = __float_as_uint(v);
    asm("mov.b64 %0, {%1, %2};" : "=l"(r) : "r"(u), "r"(u));
    return r;
}
__device__ __forceinline__ u64 fma2(u64 a, u64 b, u64 c) {
    u64 d; asm("fma.rn.f32x2 %0, %1, %2, %3;" : "=l"(d) : "l"(a), "l"(b), "l"(c));
    return d;
}
__device__ __forceinline__ float2 unpack2(u64 v) {
    unsigned lo, hi;
    asm("mov.b64 {%0, %1}, %2;" : "=r"(lo), "=r"(hi) : "l"(v));
    return make_float2(__uint_as_float(lo), __uint_as_float(hi));
}

// ---------------------------------------------------------------------------
// Kernel A: proj = feats @ W  (G x 272)@(272 x 19) -> (G x 32-padded).
// 128 threads x 2 rows. Accumulators packed across class pairs (f32x2):
// per k: 2 dup-packs + 10 uniform LDS.64 (W pairs, contiguous in row-major W)
// + 20 FFMA2  (vs 38 FFMA before -> FMA-pipe time halved).
// ---------------------------------------------------------------------------
__global__ __launch_bounds__(BLK, 3)
void proj_kernel(const float* __restrict__ feats, const float* __restrict__ Wm) {
    __shared__ float sW[D * NCP];        // W padded to 20 cols, 21.8 KB
    __shared__ float sT[RPB * TPAD];     // 256 rows x 16 k, stride 20, 20 KB

    const int tid  = threadIdx.x;
    const int base = blockIdx.x * RPB;

    for (int i = tid; i < D * NCP; i += BLK) {
        int k = i / NCP, c = i % NCP;
        sW[i] = (c < NC) ? Wm[k * NC + c] : 0.f;
    }

    u64 acc0[NCP / 2], acc1[NCP / 2];
    #pragma unroll
    for (int p = 0; p < NCP / 2; ++p) { acc0[p] = 0ull; acc1[p] = 0ull; }

    const float4* f4 = reinterpret_cast<const float4*>(feats);
    const int r0 = tid, r1 = tid + BLK;

    for (int ch = 0; ch < D / CHK; ++ch) {
        const int d4 = ch * (CHK / 4);
        __syncthreads();                 // prev-chunk reads done (covers sW iter 0)
        #pragma unroll
        for (int qq = 0; qq < 8; ++qq) {
            int i   = tid + qq * BLK;    // 0..1023 -> 256 rows x 4 float4
            int r   = i >> 2;
            int sub = i & 3;
            float4 v = f4[(size_t)(base + r) * (D / 4) + d4 + sub];
            reinterpret_cast<float4*>(&sT[r * TPAD + sub * 4])[0] = v;
        }
        __syncthreads();
        const float4* sT4 = reinterpret_cast<const float4*>(sT);
        #pragma unroll
        for (int k4 = 0; k4 < CHK / 4; ++k4) {
            float4 a = sT4[r0 * (TPAD / 4) + k4];   // 8-lane phases conflict-free
            float4 b = sT4[r1 * (TPAD / 4) + k4];
            const float av[4] = {a.x, a.y, a.z, a.w};
            const float bv[4] = {b.x, b.y, b.z, b.w};
            #pragma unroll
            for (int kk = 0; kk < 4; ++kk) {
                const int k = ch * CHK + k4 * 4 + kk;
                const u64* w2 = reinterpret_cast<const u64*>(&sW[k * NCP]);
                u64 aa = pack_dup(av[kk]);
                u64 bb = pack_dup(bv[kk]);
                #pragma unroll
                for (int p = 0; p < NCP / 2; ++p) {
                    u64 w = w2[p];                   // LDS.64 uniform broadcast
                    acc0[p] = fma2(aa, w, acc0[p]);
                    acc1[p] = fma2(bb, w, acc1[p]);
                }
            }
        }
    }

    // Unpack and write both rows (rows 128B-aligned in g_proj).
    float* o0 = &g_proj[(size_t)(base + r0) * PSTRIDE];
    float* o1 = &g_proj[(size_t)(base + r1) * PSTRIDE];
    #pragma unroll
    for (int q = 0; q < 2; ++q) {
        const u64* acc = q ? acc1 : acc0;
        float* o = q ? o1 : o0;
        float v[NCP];
        #pragma unroll
        for (int p = 0; p < NCP / 2; ++p) {
            float2 f = unpack2(acc[p]);
            v[2 * p] = f.x; v[2 * p + 1] = f.y;
        }
        #pragma unroll
        for (int c4 = 0; c4 < 4; ++c4)
            reinterpret_cast<float4*>(o)[c4] =
                make_float4(v[c4*4], v[c4*4+1], v[c4*4+2], v[c4*4+3]);
        o[16] = v[16]; o[17] = v[17]; o[18] = v[18];
    }
}

// ---------------------------------------------------------------------------
// Kernel B: 8 segments per block (1 warp each). Boundaries found inline by
// binary search on sorted seg_ids (9 searches per block, amortized). Then
// sum 19-float proj rows (L2-resident), mean, bias, sigmoid.
// ---------------------------------------------------------------------------
__global__ __launch_bounds__(256, 8)
void pool_kernel(const int* __restrict__ point_idx,
                 const int* __restrict__ seg_ids,
                 const float* __restrict__ bias,
                 float* __restrict__ out, int NI, int P)
{
    __shared__ int sb[9];
    const int tid = threadIdx.x;
    const int s0  = blockIdx.x * 8;

    if (tid < 9) {
        int target = s0 + tid;
        int lo = 0, hi = P;
        while (lo < hi) {                      // lower_bound(seg_ids, target)
            int mid = (lo + hi) >> 1;
            if (seg_ids[mid] < target) lo = mid + 1; else hi = mid;
        }
        sb[tid] = lo;
    }
    __syncthreads();

    const int w     = tid >> 5;
    const int seg   = s0 + w;
    if (seg >= NI) return;
    const int lane  = tid & 31;
    const int start = sb[w];
    const int end   = sb[w + 1];

    float acc = 0.f;
    for (int b = start; b < end; b += 32) {
        const int n = min(32, end - b);
        int myidx = (lane < n) ? point_idx[b + lane] : 0;
        int j = 0;
        for (; j + 4 <= n; j += 4) {
            int i0 = __shfl_sync(0xffffffffu, myidx, j);
            int i1 = __shfl_sync(0xffffffffu, myidx, j + 1);
            int i2 = __shfl_sync(0xffffffffu, myidx, j + 2);
            int i3 = __shfl_sync(0xffffffffu, myidx, j + 3);
            if (lane < NC) {
                float v0 = g_proj[(size_t)i0 * PSTRIDE + lane];
                float v1 = g_proj[(size_t)i1 * PSTRIDE + lane];
                float v2 = g_proj[(size_t)i2 * PSTRIDE + lane];
                float v3 = g_proj[(size_t)i3 * PSTRIDE + lane];
                acc += (v0 + v1) + (v2 + v3);
            }
        }
        for (; j < n; ++j) {
            int i0 = __shfl_sync(0xffffffffu, myidx, j);
            if (lane < NC) acc += g_proj[(size_t)i0 * PSTRIDE + lane];
        }
    }

    if (lane < NC) {
        const int cnt = max(end - start, 1);
        float z = acc / (float)cnt + bias[lane];
        out[seg * NC + lane] = 1.0f / (1.0f + expf(-z));
    }
}

// ---------------------------------------------------------------------------
// Launch
// ---------------------------------------------------------------------------
extern "C" void kernel_launch(void* const* d_in, const int* in_sizes, int n_in,
                              void* d_out, int out_size) {
    const float* feats     = (const float*)d_in[0];   // [G, D]
    const float* Wmat      = (const float*)d_in[1];   // [D, NC]
    const float* bias      = (const float*)d_in[2];   // [NC]
    const int*   point_idx = (const int*)  d_in[3];   // [P]
    const int*   seg_ids   = (const int*)  d_in[4];   // [P] sorted
    float*       out       = (float*)d_out;           // [NI, NC]

    const int P = in_sizes[3];
    int G  = in_sizes[0] / D;                         // 65536
    if (G > G_MAX) G = G_MAX;
    const int NI = out_size / NC;                     // 4096

    proj_kernel<<<G / RPB, BLK>>>(feats, Wmat);
    pool_kernel<<<(NI + 7) / 8, 256>>>(point_idx, seg_ids, bias, out, NI, P);
}